// round 16
// baseline (speedup 1.0000x reference)
#include <cuda_runtime.h>
#include <cuda_fp16.h>
#include <cstdint>
#include <cstddef>

// out_f32 = f16( f16(A[2048x4096] @ Wp[4096x4096]) @ Wu[4096x16384] )
// Legacy HMMA (tcgen05 rejected by harness ptxas target compute_103).
// R16: single fused conversion kernel + persistent fused GEMM1/GEMM2 with
// per-row-stripe dependency counters (fills G1's wave tail with G2 tiles).

#define BM 128
#define BN 256
#define BK 64
#define STAGES 3
#define PAD 8
#define A_STRIDE (BK + PAD)            // 72 halves
#define B_STRIDE (BN + PAD)            // 264 halves

#define A_STAGE_BYTES (BM * A_STRIDE * 2)                 // 18432
#define B_STAGE_BYTES (BK * B_STRIDE * 2)                 // 33792
#define SMEM_A_OFF    0
#define SMEM_B_OFF    (STAGES * A_STAGE_BYTES)
#define SMEM_DYN      (STAGES * (A_STAGE_BYTES + B_STAGE_BYTES))  // 156672

#define NSM 148        // persistent grid (guaranteed co-resident)

__device__ __half g_A  [8388608];   // fp16 A_prev
__device__ __half g_Wp [16777216];  // fp16 W_prev
__device__ __half g_Wu [67108864];  // fp16 W_up
__device__ __half g_act[8388608];   // fp16 intermediate
__device__ int    g_stripe_done[16];

__device__ __forceinline__ uint32_t smem_u32(const void* p) {
    return (uint32_t)__cvta_generic_to_shared(p);
}

// ---------------------------------------------------------------------------
// One kernel converts all three fp32 inputs to fp16 (552 MB of traffic).
__global__ void conv_all(const float4* __restrict__ A,
                         const float4* __restrict__ Wp,
                         const float4* __restrict__ Wu)
{
    const long long nA = 2097152, nWp = 4194304, nWu = 16777216;  // float4 counts
    const long long total = nA + nWp + nWu;
    const long long stride = (long long)gridDim.x * blockDim.x;
    for (long long i = (long long)blockIdx.x * blockDim.x + threadIdx.x;
         i < total; i += stride) {
        const float4* s; __half2* d; long long j;
        if (i < nA)            { s = A;  d = (__half2*)g_A;  j = i; }
        else if (i < nA + nWp) { s = Wp; d = (__half2*)g_Wp; j = i - nA; }
        else                   { s = Wu; d = (__half2*)g_Wu; j = i - nA - nWp; }
        float4 v = s[j];
        d[2 * j + 0] = __floats2half2_rn(v.x, v.y);
        d[2 * j + 1] = __floats2half2_rn(v.z, v.w);
    }
}

__global__ void reset_flags() {
    if (threadIdx.x < 16) g_stripe_done[threadIdx.x] = 0;
}

// ---------------------------------------------------------------------------
// Persistent fused GEMM. Tiles 0..255 = GEMM1 (act = f16(A@Wp), 16x16 grid,
// stripe-major). Tiles 256..1279 = GEMM2 (out = f16(act@Wu), 16x64).
// A GEMM2 tile for m-stripe s waits until all 16 GEMM1 tiles of stripe s done.
__global__ __launch_bounds__(512, 1) void gemm_fused(float* __restrict__ out)
{
    extern __shared__ char smem[];
    const uint32_t sbA = smem_u32(smem) + SMEM_A_OFF;
    const uint32_t sbB = smem_u32(smem) + SMEM_B_OFF;

    const int tid  = threadIdx.x;
    const int lane = tid & 31;
    const int warp = tid >> 5;
    const int wr   = warp & 1;    // 2 warps along M (64 rows each)
    const int wc   = warp >> 1;   // 8 warps along N (32 cols each)
    const int K    = 4096;
    const int ntiles = K / BK;    // 64

    for (int t = blockIdx.x; t < 1280; t += NSM) {
        const bool g1  = (t < 256);
        const int  u   = g1 ? t : (t - 256);
        const int  bm_i = g1 ? (u >> 4) : (u >> 6);
        const int  N    = g1 ? 4096 : 16384;
        const int  bm   = bm_i * BM;
        const int  bn   = (g1 ? (u & 15) : (u & 63)) * BN;
        const __half* Ag = g1 ? (const __half*)g_A  : (const __half*)g_act;
        const __half* Bg = g1 ? (const __half*)g_Wp : (const __half*)g_Wu;

        __syncthreads();   // previous tile's smem reads done before reuse

        if (!g1) {         // wait for this m-stripe of g_act
            if (tid == 0) {
                int v;
                while (true) {
                    asm volatile("ld.acquire.gpu.global.s32 %0, [%1];"
                                 : "=r"(v) : "l"(&g_stripe_done[bm_i]) : "memory");
                    if (v >= 16) break;
                    __nanosleep(128);
                }
            }
            __syncthreads();
        }

        float acc[4][4][4];
        #pragma unroll
        for (int i = 0; i < 4; i++)
            #pragma unroll
            for (int j = 0; j < 4; j++)
                #pragma unroll
                for (int r = 0; r < 4; r++) acc[i][j][r] = 0.f;

        auto load_tiles = [&](int s, int k0) {
            uint32_t aBase = sbA + s * A_STAGE_BYTES;
            uint32_t bBase = sbB + s * B_STAGE_BYTES;
            #pragma unroll
            for (int i = 0; i < 2; i++) {            // A: 1024 x 16B chunks
                int tt  = tid + i * 512;
                int row = tt >> 3;
                int col = (tt & 7) << 3;
                uint32_t dst = aBase + (uint32_t)(row * A_STRIDE + col) * 2;
                const __half* src = Ag + (size_t)(bm + row) * K + (k0 + col);
                asm volatile("cp.async.cg.shared.global [%0], [%1], 16;"
                             :: "r"(dst), "l"(src) : "memory");
            }
            #pragma unroll
            for (int i = 0; i < 4; i++) {            // B: 2048 x 16B chunks
                int tt  = tid + i * 512;
                int row = tt >> 5;
                int col = (tt & 31) << 3;
                uint32_t dst = bBase + (uint32_t)(row * B_STRIDE + col) * 2;
                const __half* src = Bg + (size_t)(k0 + row) * N + (bn + col);
                asm volatile("cp.async.cg.shared.global [%0], [%1], 16;"
                             :: "r"(dst), "l"(src) : "memory");
            }
            asm volatile("cp.async.commit_group;" ::: "memory");
        };

        #pragma unroll
        for (int s = 0; s < STAGES - 1; s++)
            load_tiles(s, s * BK);

        for (int kt = 0; kt < ntiles; kt++) {
            const int s = kt % STAGES;
            asm volatile("cp.async.wait_group %0;" :: "n"(STAGES - 2) : "memory");
            if (kt == ntiles - 1)
                asm volatile("cp.async.wait_group 0;" ::: "memory");
            __syncthreads();
            if (kt + STAGES - 1 < ntiles)
                load_tiles((kt + STAGES - 1) % STAGES, (kt + STAGES - 1) * BK);

            uint32_t aBase = sbA + s * A_STAGE_BYTES;
            uint32_t bBase = sbB + s * B_STAGE_BYTES;

            #pragma unroll
            for (int ks = 0; ks < 4; ks++) {          // 4 x k16 per BK=64
                uint32_t a[4][4];
                uint32_t b[2][4];
                #pragma unroll
                for (int i = 0; i < 4; i++) {
                    int row = wr * 64 + i * 16 + (lane & 15);
                    int col = ks * 16 + ((lane >> 4) << 3);
                    uint32_t addr = aBase + (uint32_t)(row * A_STRIDE + col) * 2;
                    asm volatile("ldmatrix.sync.aligned.m8n8.x4.shared.b16 {%0,%1,%2,%3}, [%4];"
                                 : "=r"(a[i][0]), "=r"(a[i][1]), "=r"(a[i][2]), "=r"(a[i][3])
                                 : "r"(addr));
                }
                #pragma unroll
                for (int jj = 0; jj < 2; jj++) {
                    int row = ks * 16 + (lane & 15);
                    int col = wc * 32 + jj * 16 + ((lane >> 4) << 3);
                    uint32_t addr = bBase + (uint32_t)(row * B_STRIDE + col) * 2;
                    asm volatile("ldmatrix.sync.aligned.m8n8.x4.trans.shared.b16 {%0,%1,%2,%3}, [%4];"
                                 : "=r"(b[jj][0]), "=r"(b[jj][1]), "=r"(b[jj][2]), "=r"(b[jj][3])
                                 : "r"(addr));
                }
                #pragma unroll
                for (int i = 0; i < 4; i++)
                    #pragma unroll
                    for (int j = 0; j < 4; j++) {
                        const uint32_t b0 = b[j >> 1][(j & 1) * 2 + 0];
                        const uint32_t b1 = b[j >> 1][(j & 1) * 2 + 1];
                        asm volatile(
                            "mma.sync.aligned.m16n8k16.row.col.f32.f16.f16.f32 "
                            "{%0,%1,%2,%3}, {%4,%5,%6,%7}, {%8,%9}, {%0,%1,%2,%3};"
                            : "+f"(acc[i][j][0]), "+f"(acc[i][j][1]),
                              "+f"(acc[i][j][2]), "+f"(acc[i][j][3])
                            : "r"(a[i][0]), "r"(a[i][1]), "r"(a[i][2]), "r"(a[i][3]),
                              "r"(b0), "r"(b1));
                    }
            }
        }

        // Epilogue: fp32 acc -> fp16 round (matches reference astype(float16)).
        #pragma unroll
        for (int i = 0; i < 4; i++) {
            #pragma unroll
            for (int j = 0; j < 4; j++) {
                int row0 = bm + wr * 64 + i * 16 + (lane >> 2);
                int col  = bn + wc * 32 + j * 8 + (lane & 3) * 2;
                __half2 h01 = __floats2half2_rn(acc[i][j][0], acc[i][j][1]);
                __half2 h23 = __floats2half2_rn(acc[i][j][2], acc[i][j][3]);
                if (g1) {
                    *(__half2*)(g_act + (size_t)row0 * N + col) = h01;
                    *(__half2*)(g_act + (size_t)(row0 + 8) * N + col) = h23;
                } else {
                    *(float2*)(out + (size_t)row0 * N + col) =
                        make_float2(__half2float(__low2half(h01)), __half2float(__high2half(h01)));
                    *(float2*)(out + (size_t)(row0 + 8) * N + col) =
                        make_float2(__half2float(__low2half(h23)), __half2float(__high2half(h23)));
                }
            }
        }

        if (g1) {   // publish this G1 tile: all stores visible, then count it
            __threadfence();
            __syncthreads();
            if (tid == 0) atomicAdd(&g_stripe_done[bm_i], 1);
        }
    }
}

extern "C" void kernel_launch(void* const* d_in, const int* in_sizes, int n_in,
                              void* d_out, int out_size)
{
    (void)out_size;
    const float* A  = (const float*)d_in[0];
    const float* Wp = (n_in > 1) ? (const float*)d_in[1] : A;
    const float* Wu = (n_in > 2) ? (const float*)d_in[2] : A;
    for (int i = 0; i < n_in; i++) {
        if      (in_sizes[i] == 8388608)  A  = (const float*)d_in[i];
        else if (in_sizes[i] == 16777216) Wp = (const float*)d_in[i];
        else if (in_sizes[i] == 67108864) Wu = (const float*)d_in[i];
    }
    float* out = (float*)d_out;  // [2048, 16384] float32

    cudaFuncSetAttribute(gemm_fused,
                         cudaFuncAttributeMaxDynamicSharedMemorySize, SMEM_DYN);

    conv_all<<<4096, 256>>>((const float4*)A, (const float4*)Wp, (const float4*)Wu);
    reset_flags<<<1, 32>>>();
    gemm_fused<<<NSM, 512, SMEM_DYN>>>(out);
}

// round 17
// speedup vs baseline: 1.0276x; 1.0276x over previous
#include <cuda_runtime.h>
#include <cuda_fp16.h>
#include <cstdint>
#include <cstddef>

// out_f32 = f16( f16(A[2048x4096] @ Wp[4096x4096]) @ Wu[4096x16384] )
// Legacy HMMA (tcgen05 rejected by harness ptxas target compute_103).
// R17: best-of-measured composition — R16's fused conversion kernel (81.5us,
// 80% of DRAM roofline) + R13/R15's GEMM pair (tensor-ceiling-bound cores).

#define BM 128
#define BN 256
#define BK 64
#define STAGES 3
#define PAD 8
#define A_STRIDE (BK + PAD)            // 72 halves
#define B_STRIDE (BN + PAD)            // 264 halves

#define A_STAGE_BYTES (BM * A_STRIDE * 2)                 // 18432
#define B_STAGE_BYTES (BK * B_STRIDE * 2)                 // 33792
#define SMEM_A_OFF    0
#define SMEM_B_OFF    (STAGES * A_STAGE_BYTES)
#define SMEM_DYN      (STAGES * (A_STAGE_BYTES + B_STAGE_BYTES))  // 156672

__device__ __half g_A  [8388608];   // fp16 A_prev
__device__ __half g_Wp [16777216];  // fp16 W_prev
__device__ __half g_Wu [67108864];  // fp16 W_up
__device__ __half g_act[8388608];   // fp16 intermediate

__device__ __forceinline__ uint32_t smem_u32(const void* p) {
    return (uint32_t)__cvta_generic_to_shared(p);
}

// ---------------------------------------------------------------------------
// One kernel converts all three fp32 inputs to fp16 (552 MB of traffic,
// measured 6.4 TB/s = 80.8% of DRAM).
__global__ void conv_all(const float4* __restrict__ A,
                         const float4* __restrict__ Wp,
                         const float4* __restrict__ Wu)
{
    const long long nA = 2097152, nWp = 4194304, nWu = 16777216;  // float4 counts
    const long long total = nA + nWp + nWu;
    const long long stride = (long long)gridDim.x * blockDim.x;
    for (long long i = (long long)blockIdx.x * blockDim.x + threadIdx.x;
         i < total; i += stride) {
        const float4* s; __half2* d; long long j;
        if (i < nA)            { s = A;  d = (__half2*)g_A;  j = i; }
        else if (i < nA + nWp) { s = Wp; d = (__half2*)g_Wp; j = i - nA; }
        else                   { s = Wu; d = (__half2*)g_Wu; j = i - nA - nWp; }
        float4 v = s[j];
        d[2 * j + 0] = __floats2half2_rn(v.x, v.y);
        d[2 * j + 1] = __floats2half2_rn(v.z, v.w);
    }
}

// ---------------------------------------------------------------------------
// fp16 GEMM: CTA 128x256, 16 warps as 2(M) x 8(N), warp tile 64x32.  (= R13)
template<bool STAGE2>
__global__ __launch_bounds__(512, 1) void gemm_f16_mma(
    float* __restrict__ Cout, int M, int N, int K)
{
    extern __shared__ char smem[];
    const uint32_t sbA = smem_u32(smem) + SMEM_A_OFF;
    const uint32_t sbB = smem_u32(smem) + SMEM_B_OFF;

    const __half* A  = STAGE2 ? (const __half*)g_act : (const __half*)g_A;
    const __half* Bm = STAGE2 ? (const __half*)g_Wu  : (const __half*)g_Wp;

    const int tid  = threadIdx.x;
    const int lane = tid & 31;
    const int warp = tid >> 5;
    const int wr   = warp & 1;
    const int wc   = warp >> 1;

    const int bm = blockIdx.y * BM;
    const int bn = blockIdx.x * BN;

    float acc[4][4][4];
    #pragma unroll
    for (int i = 0; i < 4; i++)
        #pragma unroll
        for (int j = 0; j < 4; j++)
            #pragma unroll
            for (int r = 0; r < 4; r++) acc[i][j][r] = 0.f;

    auto load_tiles = [&](int s, int k0) {
        uint32_t aBase = sbA + s * A_STAGE_BYTES;
        uint32_t bBase = sbB + s * B_STAGE_BYTES;
        #pragma unroll
        for (int i = 0; i < 2; i++) {            // A: 1024 x 16B chunks
            int t   = tid + i * 512;
            int row = t >> 3;
            int col = (t & 7) << 3;
            uint32_t dst = aBase + (uint32_t)(row * A_STRIDE + col) * 2;
            const __half* src = A + (size_t)(bm + row) * K + (k0 + col);
            asm volatile("cp.async.cg.shared.global [%0], [%1], 16;"
                         :: "r"(dst), "l"(src) : "memory");
        }
        #pragma unroll
        for (int i = 0; i < 4; i++) {            // B: 2048 x 16B chunks
            int t   = tid + i * 512;
            int row = t >> 5;
            int col = (t & 31) << 3;
            uint32_t dst = bBase + (uint32_t)(row * B_STRIDE + col) * 2;
            const __half* src = Bm + (size_t)(k0 + row) * N + (bn + col);
            asm volatile("cp.async.cg.shared.global [%0], [%1], 16;"
                         :: "r"(dst), "l"(src) : "memory");
        }
        asm volatile("cp.async.commit_group;" ::: "memory");
    };

    const int ntiles = K / BK;   // 64

    #pragma unroll
    for (int s = 0; s < STAGES - 1; s++)
        load_tiles(s, s * BK);

    for (int kt = 0; kt < ntiles; kt++) {
        const int s = kt % STAGES;
        asm volatile("cp.async.wait_group %0;" :: "n"(STAGES - 2) : "memory");
        __syncthreads();
        if (kt + STAGES - 1 < ntiles)
            load_tiles((kt + STAGES - 1) % STAGES, (kt + STAGES - 1) * BK);

        uint32_t aBase = sbA + s * A_STAGE_BYTES;
        uint32_t bBase = sbB + s * B_STAGE_BYTES;

        #pragma unroll
        for (int ks = 0; ks < 4; ks++) {          // 4 x k16 per BK=64
            uint32_t a[4][4];
            uint32_t b[2][4];
            #pragma unroll
            for (int i = 0; i < 4; i++) {
                int row = wr * 64 + i * 16 + (lane & 15);
                int col = ks * 16 + ((lane >> 4) << 3);
                uint32_t addr = aBase + (uint32_t)(row * A_STRIDE + col) * 2;
                asm volatile("ldmatrix.sync.aligned.m8n8.x4.shared.b16 {%0,%1,%2,%3}, [%4];"
                             : "=r"(a[i][0]), "=r"(a[i][1]), "=r"(a[i][2]), "=r"(a[i][3])
                             : "r"(addr));
            }
            #pragma unroll
            for (int jj = 0; jj < 2; jj++) {
                int row = ks * 16 + (lane & 15);
                int col = wc * 32 + jj * 16 + ((lane >> 4) << 3);
                uint32_t addr = bBase + (uint32_t)(row * B_STRIDE + col) * 2;
                asm volatile("ldmatrix.sync.aligned.m8n8.x4.trans.shared.b16 {%0,%1,%2,%3}, [%4];"
                             : "=r"(b[jj][0]), "=r"(b[jj][1]), "=r"(b[jj][2]), "=r"(b[jj][3])
                             : "r"(addr));
            }
            #pragma unroll
            for (int i = 0; i < 4; i++)
                #pragma unroll
                for (int j = 0; j < 4; j++) {
                    const uint32_t b0 = b[j >> 1][(j & 1) * 2 + 0];
                    const uint32_t b1 = b[j >> 1][(j & 1) * 2 + 1];
                    asm volatile(
                        "mma.sync.aligned.m16n8k16.row.col.f32.f16.f16.f32 "
                        "{%0,%1,%2,%3}, {%4,%5,%6,%7}, {%8,%9}, {%0,%1,%2,%3};"
                        : "+f"(acc[i][j][0]), "+f"(acc[i][j][1]),
                          "+f"(acc[i][j][2]), "+f"(acc[i][j][3])
                        : "r"(a[i][0]), "r"(a[i][1]), "r"(a[i][2]), "r"(a[i][3]),
                          "r"(b0), "r"(b1));
                }
        }
    }

    // Epilogue: fp32 acc -> fp16 round (bit-matches reference astype(float16)).
    #pragma unroll
    for (int i = 0; i < 4; i++) {
        #pragma unroll
        for (int j = 0; j < 4; j++) {
            int row0 = bm + wr * 64 + i * 16 + (lane >> 2);
            int col  = bn + wc * 32 + j * 8 + (lane & 3) * 2;
            __half2 h01 = __floats2half2_rn(acc[i][j][0], acc[i][j][1]);
            __half2 h23 = __floats2half2_rn(acc[i][j][2], acc[i][j][3]);
            if (!STAGE2) {
                *(__half2*)(g_act + (size_t)row0 * N + col) = h01;
                *(__half2*)(g_act + (size_t)(row0 + 8) * N + col) = h23;
            } else {
                *(float2*)(Cout + (size_t)row0 * N + col) =
                    make_float2(__half2float(__low2half(h01)), __half2float(__high2half(h01)));
                *(float2*)(Cout + (size_t)(row0 + 8) * N + col) =
                    make_float2(__half2float(__low2half(h23)), __half2float(__high2half(h23)));
            }
        }
    }
}

extern "C" void kernel_launch(void* const* d_in, const int* in_sizes, int n_in,
                              void* d_out, int out_size)
{
    (void)out_size;
    const float* A  = (const float*)d_in[0];
    const float* Wp = (n_in > 1) ? (const float*)d_in[1] : A;
    const float* Wu = (n_in > 2) ? (const float*)d_in[2] : A;
    for (int i = 0; i < n_in; i++) {
        if      (in_sizes[i] == 8388608)  A  = (const float*)d_in[i];
        else if (in_sizes[i] == 16777216) Wp = (const float*)d_in[i];
        else if (in_sizes[i] == 67108864) Wu = (const float*)d_in[i];
    }
    float* out = (float*)d_out;  // [2048, 16384] float32

    cudaFuncSetAttribute(gemm_f16_mma<false>,
                         cudaFuncAttributeMaxDynamicSharedMemorySize, SMEM_DYN);
    cudaFuncSetAttribute(gemm_f16_mma<true>,
                         cudaFuncAttributeMaxDynamicSharedMemorySize, SMEM_DYN);

    const int Bdim = 2048, Ddim = 4096, Kdim = 4096, Fdim = 16384;
    dim3 blk(512);

    // Single fused fp32->fp16 conversion for A, Wp, Wu (DRAM-roofline bound).
    conv_all<<<4096, 256>>>((const float4*)A, (const float4*)Wp, (const float4*)Wu);

    // GEMM1: g_act = f16(A @ Wp)   [2048 x 4096]
    gemm_f16_mma<false><<<dim3(Ddim / BN, Bdim / BM), blk, SMEM_DYN>>>(nullptr, Bdim, Ddim, Kdim);
    // GEMM2: out = f16(g_act @ Wu) [2048 x 16384] stored fp32
    gemm_f16_mma<true><<<dim3(Fdim / BN, Bdim / BM), blk, SMEM_DYN>>>(out, Bdim, Fdim, Ddim);
}